// round 12
// baseline (speedup 1.0000x reference)
#include <cuda_runtime.h>
#include <cstdint>

// Problem geometry: frames (4,8,2,4,480,640) fp32 -> dense (32, 8, 480, 640)
#define CH         8u           // N_evt*C_evt = 2*4
#define HW         307200u      // 480*640
#define WIDTH      640u
#define TILE       4096u        // pixels per tile (307200 = 75*4096 -> tile within one bf)
#define NTILES     2400u
#define THREADS    256
#define MAXPTS     200000u
#define FEAT_OFF   0u
#define COORD_OFF  1600000u     // 200000*8
#define THRESH     3.0f

// Epoch-tagged decoupled-lookback state (NO per-launch reset needed):
//   high 32 bits = epoch*4 + state   (state: 0 invalid, 1 aggregate, 2 prefix)
//   low  32 bits = value
// Zero-initialized __device__ globals give epoch=0/state=invalid at t=0; each
// launch advances epoch via the monotone tile counter, so stale entries from
// earlier graph replays are automatically "not ready".
__device__ unsigned long long g_status[NTILES];   // zero-init
__device__ unsigned int       g_tile_counter;     // zero-init, never reset

__device__ __forceinline__ float4 fabs4(float4 v) {
    return make_float4(fabsf(v.x), fabsf(v.y), fabsf(v.z), fabsf(v.w));
}
__device__ __forceinline__ float4 max4(float4 a, float4 b) {
    return make_float4(fmaxf(a.x, b.x), fmaxf(a.y, b.y), fmaxf(a.z, b.z), fmaxf(a.w, b.w));
}

// ---------------------------------------------------------------------------
// Single-pass ordered compaction with epoch-based decoupled lookback.
// launch_bounds(256,5): ~48 regs -> 40 warps/SM so 5 blocks overlap their
// scan/lookback/scatter phases with other blocks' streaming loads.
// ---------------------------------------------------------------------------
__global__ __launch_bounds__(THREADS, 5) void voxelizer_kernel(
    const float* __restrict__ in, float* __restrict__ out)
{
    __shared__ unsigned short s_hits[TILE];  // tile-local pixel index, in order
    __shared__ unsigned s_warp[8];           // packed per-iter warp totals
    __shared__ unsigned s_raw;
    __shared__ unsigned s_excl;

    const int tid  = threadIdx.x;
    const int lane = tid & 31;
    const int wid  = tid >> 5;

    if (tid == 0) s_raw = atomicAdd(&g_tile_counter, 1u);
    __syncthreads();
    const unsigned raw   = s_raw;
    const unsigned tile  = raw % NTILES;
    const unsigned epoch = raw / NTILES;

    const unsigned bf = tile / 75u;               // tile fully within one bf slice
    const unsigned p_base = (tile % 75u) * TILE;  // pixel offset within the bf slice
    const float4* __restrict__ slice4 =
        reinterpret_cast<const float4*>(in + (size_t)bf * (CH * HW));

    // ---- Phase 1: stream the tile, build 16-bit hit mask (4 iters x 4 px) ----
    // v[4] staging x2: MLP=4 per batch at ~48 regs, enabling 40 warps/SM.
    unsigned hm16 = 0u;
    #pragma unroll
    for (int it = 0; it < 4; ++it) {
        const unsigned local0 = (unsigned)it * 1024u + (unsigned)tid * 4u;
        const float4* b4 = slice4 + ((p_base + local0) >> 2);

        float4 v[4];
        #pragma unroll
        for (int c = 0; c < 4; ++c)
            v[c] = b4[(size_t)c * (HW / 4u)];
        float4 mx = fabs4(v[0]);
        #pragma unroll
        for (int c = 1; c < 4; ++c)
            mx = max4(mx, fabs4(v[c]));
        #pragma unroll
        for (int c = 0; c < 4; ++c)
            v[c] = b4[(size_t)(c + 4) * (HW / 4u)];
        #pragma unroll
        for (int c = 0; c < 4; ++c)
            mx = max4(mx, fabs4(v[c]));

        unsigned hm = (mx.x > THRESH ? 1u : 0u) |
                      (mx.y > THRESH ? 2u : 0u) |
                      (mx.z > THRESH ? 4u : 0u) |
                      (mx.w > THRESH ? 8u : 0u);
        hm16 |= hm << (it * 4);
    }

    // ---- Phase 2: one packed scan (4 byte-fields, one per iteration) ----
    unsigned cnt[4];
    unsigned packed = 0u;
    #pragma unroll
    for (int i = 0; i < 4; ++i) {
        cnt[i] = (unsigned)__popc((hm16 >> (4 * i)) & 0xFu);
        packed |= cnt[i] << (8 * i);
    }

    unsigned incl = packed;   // warp-inclusive scan; fields max 128, no overflow
    #pragma unroll
    for (int o = 1; o < 32; o <<= 1) {
        unsigned n = __shfl_up_sync(0xffffffffu, incl, o);
        if (lane >= o) incl += n;
    }
    if (lane == 31) s_warp[wid] = incl;
    __syncthreads();

    unsigned wexcl[4] = {0u, 0u, 0u, 0u};
    unsigned tot[4]   = {0u, 0u, 0u, 0u};
    #pragma unroll
    for (int w = 0; w < 8; ++w) {
        unsigned v = s_warp[w];
        #pragma unroll
        for (int i = 0; i < 4; ++i) {
            unsigned f = (v >> (8 * i)) & 0xFFu;
            if (w < wid) wexcl[i] += f;
            tot[i] += f;
        }
    }
    unsigned iter_base[4];
    iter_base[0] = 0u;
    iter_base[1] = tot[0];
    iter_base[2] = tot[0] + tot[1];
    iter_base[3] = tot[0] + tot[1] + tot[2];
    const unsigned tile_total = iter_base[3] + tot[3];

    // Publish aggregate ASAP (tile 0 publishes its prefix directly).
    if (tid == 0) {
        unsigned state = (tile == 0u) ? 2u : 1u;
        unsigned long long word =
            ((unsigned long long)(epoch * 4u + state) << 32) | tile_total;
        __threadfence();
        atomicExch(&g_status[tile], word);
        if (tile == 0u) s_excl = 0u;
    }

    // ---- Phase 3: ordered write of hit indices into shared ----
    #pragma unroll
    for (int it = 0; it < 4; ++it) {
        unsigned hm = (hm16 >> (4 * it)) & 0xFu;
        if (hm) {
            unsigned local0 = (unsigned)it * 1024u + (unsigned)tid * 4u;
            unsigned idx = iter_base[it] + wexcl[it] + ((incl >> (8 * it)) & 0xFFu) - cnt[it];
            #pragma unroll
            for (int j = 0; j < 4; ++j)
                if ((hm >> j) & 1u) s_hits[idx++] = (unsigned short)(local0 + j);
        }
    }

    // ---- Phase 4: warp-parallel epoch-checked decoupled lookback (warp 0) ----
    if (wid == 0 && tile > 0u) {
        unsigned excl = 0u;
        int wbase = (int)tile;
        const unsigned long long ep4 = (unsigned long long)(epoch * 4u);
        while (true) {
            int idx = wbase - 32 + lane;
            unsigned long long s;
            unsigned hi, state;
            do {
                if (idx >= 0) {
                    s = *(volatile unsigned long long*)&g_status[idx];
                    hi = (unsigned)(s >> 32);
                    // ready iff same epoch and state != 0
                    state = (hi >> 2 == epoch) ? (hi & 3u) : 0u;
                } else {
                    s = 0ull;           // virtual prefix=0 before tile 0
                    state = 2u;
                }
            } while (__any_sync(0xffffffffu, state == 0u));

            unsigned pmask = __ballot_sync(0xffffffffu, state == 2u);
            unsigned contrib;
            int done;
            if (pmask) {
                int h = 31 - __clz(pmask);       // highest lane holding a prefix
                contrib = (lane >= h) ? (unsigned)(s & 0xffffffffull) : 0u;
                done = 1;
            } else {
                contrib = (unsigned)(s & 0xffffffffull);
                done = 0;
            }
            #pragma unroll
            for (int o = 16; o; o >>= 1)
                contrib += __shfl_down_sync(0xffffffffu, contrib, o);
            contrib = __shfl_sync(0xffffffffu, contrib, 0);
            excl += contrib;
            if (done) break;
            wbase -= 32;
        }
        if (lane == 0) {
            s_excl = excl;
            unsigned long long word =
                ((unsigned long long)(epoch * 4u + 2u) << 32) |
                (unsigned long long)(excl + tile_total);
            __threadfence();
            atomicExch(&g_status[tile], word);
        }
    }
    __syncthreads();
    const unsigned excl = s_excl;

    // ---- Phase 5a: last tile zeroes the invalid tail (output is poisoned) ----
    if (tile == NTILES - 1u) {
        unsigned total = excl + tile_total;
        if (total < MAXPTS) {
            for (unsigned r = total + (unsigned)tid; r < MAXPTS; r += THREADS) {
                float4* f4 = reinterpret_cast<float4*>(out + FEAT_OFF + (size_t)r * 8u);
                f4[0] = make_float4(0.f, 0.f, 0.f, 0.f);
                f4[1] = make_float4(0.f, 0.f, 0.f, 0.f);
                *reinterpret_cast<float4*>(out + COORD_OFF + (size_t)r * 4u) =
                    make_float4(0.f, 0.f, 0.f, 0.f);
            }
        }
    }

    if (excl >= MAXPTS) return;   // nothing from this tile fits

    // ---- Phase 5b: scatter (feature re-reads hit L1/L2 — tile just streamed) ----
    for (unsigned j = tid; j < tile_total; j += THREADS) {
        unsigned rank = excl + j;
        if (rank >= MAXPTS) break;
        unsigned p = p_base + (unsigned)s_hits[j];
        const float* src = in + (size_t)bf * (CH * HW) + p;
        float* f = out + FEAT_OFF + (size_t)rank * 8u;
        #pragma unroll
        for (int c = 0; c < 8; ++c)
            f[c] = __ldg(src + (size_t)c * HW);
        float* cd = out + COORD_OFF + (size_t)rank * 4u;
        cd[0] = (float)(bf >> 3);      // batch = bf / S (S=8)
        cd[1] = (float)(bf & 7u);      // time  = bf % S
        cd[2] = (float)(p / WIDTH);    // y
        cd[3] = (float)(p % WIDTH);    // x
    }
}

// ---------------------------------------------------------------------------
extern "C" void kernel_launch(void* const* d_in, const int* in_sizes, int n_in,
                              void* d_out, int out_size)
{
    const float* frames = (const float*)d_in[0];
    float* out = (float*)d_out;

    voxelizer_kernel<<<NTILES, THREADS>>>(frames, out);
}

// round 13
// speedup vs baseline: 1.0277x; 1.0277x over previous
#include <cuda_runtime.h>
#include <cstdint>

// Problem geometry: frames (4,8,2,4,480,640) fp32 -> dense (32, 8, 480, 640)
#define CH         8u           // N_evt*C_evt = 2*4
#define HW         307200u      // 480*640
#define WIDTH      640u
#define TILE       4096u        // pixels per tile (307200 = 75*4096 -> tile within one bf)
#define NTILES     2400u
#define THREADS    256
#define MAXPTS     200000u
#define FEAT_OFF   0u
#define COORD_OFF  1600000u     // 200000*8
#define THRESH     3.0f

// Epoch-tagged decoupled-lookback state (NO per-launch reset needed):
//   high 32 bits = epoch*4 + state   (state: 0 invalid, 1 aggregate, 2 prefix)
//   low  32 bits = value
// Zero-initialized __device__ globals give epoch=0/state=invalid at t=0; each
// launch advances epoch via the monotone tile counter, so stale entries from
// earlier graph replays are automatically "not ready".
__device__ unsigned long long g_status[NTILES];   // zero-init
__device__ unsigned int       g_tile_counter;     // zero-init, never reset

__device__ __forceinline__ float4 fabs4(float4 v) {
    return make_float4(fabsf(v.x), fabsf(v.y), fabsf(v.z), fabsf(v.w));
}
__device__ __forceinline__ float4 max4(float4 a, float4 b) {
    return make_float4(fmaxf(a.x, b.x), fmaxf(a.y, b.y), fmaxf(a.z, b.z), fmaxf(a.w, b.w));
}

// ---------------------------------------------------------------------------
// Single-pass ordered compaction with epoch-based decoupled lookback.
// launch_bounds(256,5): ~48 regs -> 40 warps/SM so 5 blocks overlap their
// scan/lookback/scatter phases with other blocks' streaming loads.
// ---------------------------------------------------------------------------
__global__ __launch_bounds__(THREADS, 5) void voxelizer_kernel(
    const float* __restrict__ in, float* __restrict__ out)
{
    __shared__ unsigned short s_hits[TILE];  // tile-local pixel index, in order
    __shared__ unsigned s_warp[8];           // packed per-iter warp totals
    __shared__ unsigned s_raw;
    __shared__ unsigned s_excl;

    const int tid  = threadIdx.x;
    const int lane = tid & 31;
    const int wid  = tid >> 5;

    if (tid == 0) s_raw = atomicAdd(&g_tile_counter, 1u);
    __syncthreads();
    const unsigned raw   = s_raw;
    const unsigned tile  = raw % NTILES;
    const unsigned epoch = raw / NTILES;

    const unsigned bf = tile / 75u;               // tile fully within one bf slice
    const unsigned p_base = (tile % 75u) * TILE;  // pixel offset within the bf slice
    const float4* __restrict__ slice4 =
        reinterpret_cast<const float4*>(in + (size_t)bf * (CH * HW));

    // ---- Phase 1: stream the tile, build 16-bit hit mask (4 iters x 4 px) ----
    // v[4] staging x2: MLP=4 per batch at ~48 regs, enabling 40 warps/SM.
    unsigned hm16 = 0u;
    #pragma unroll
    for (int it = 0; it < 4; ++it) {
        const unsigned local0 = (unsigned)it * 1024u + (unsigned)tid * 4u;
        const float4* b4 = slice4 + ((p_base + local0) >> 2);

        float4 v[4];
        #pragma unroll
        for (int c = 0; c < 4; ++c)
            v[c] = b4[(size_t)c * (HW / 4u)];
        float4 mx = fabs4(v[0]);
        #pragma unroll
        for (int c = 1; c < 4; ++c)
            mx = max4(mx, fabs4(v[c]));
        #pragma unroll
        for (int c = 0; c < 4; ++c)
            v[c] = b4[(size_t)(c + 4) * (HW / 4u)];
        #pragma unroll
        for (int c = 0; c < 4; ++c)
            mx = max4(mx, fabs4(v[c]));

        unsigned hm = (mx.x > THRESH ? 1u : 0u) |
                      (mx.y > THRESH ? 2u : 0u) |
                      (mx.z > THRESH ? 4u : 0u) |
                      (mx.w > THRESH ? 8u : 0u);
        hm16 |= hm << (it * 4);
    }

    // ---- Phase 2: one packed scan (4 byte-fields, one per iteration) ----
    unsigned cnt[4];
    unsigned packed = 0u;
    #pragma unroll
    for (int i = 0; i < 4; ++i) {
        cnt[i] = (unsigned)__popc((hm16 >> (4 * i)) & 0xFu);
        packed |= cnt[i] << (8 * i);
    }

    unsigned incl = packed;   // warp-inclusive scan; fields max 128, no overflow
    #pragma unroll
    for (int o = 1; o < 32; o <<= 1) {
        unsigned n = __shfl_up_sync(0xffffffffu, incl, o);
        if (lane >= o) incl += n;
    }
    if (lane == 31) s_warp[wid] = incl;
    __syncthreads();

    unsigned wexcl[4] = {0u, 0u, 0u, 0u};
    unsigned tot[4]   = {0u, 0u, 0u, 0u};
    #pragma unroll
    for (int w = 0; w < 8; ++w) {
        unsigned v = s_warp[w];
        #pragma unroll
        for (int i = 0; i < 4; ++i) {
            unsigned f = (v >> (8 * i)) & 0xFFu;
            if (w < wid) wexcl[i] += f;
            tot[i] += f;
        }
    }
    unsigned iter_base[4];
    iter_base[0] = 0u;
    iter_base[1] = tot[0];
    iter_base[2] = tot[0] + tot[1];
    iter_base[3] = tot[0] + tot[1] + tot[2];
    const unsigned tile_total = iter_base[3] + tot[3];

    // Publish aggregate ASAP (tile 0 publishes its prefix directly).
    if (tid == 0) {
        unsigned state = (tile == 0u) ? 2u : 1u;
        unsigned long long word =
            ((unsigned long long)(epoch * 4u + state) << 32) | tile_total;
        __threadfence();
        atomicExch(&g_status[tile], word);
        if (tile == 0u) s_excl = 0u;
    }

    // ---- Phase 3: ordered write of hit indices into shared ----
    #pragma unroll
    for (int it = 0; it < 4; ++it) {
        unsigned hm = (hm16 >> (4 * it)) & 0xFu;
        if (hm) {
            unsigned local0 = (unsigned)it * 1024u + (unsigned)tid * 4u;
            unsigned idx = iter_base[it] + wexcl[it] + ((incl >> (8 * it)) & 0xFFu) - cnt[it];
            #pragma unroll
            for (int j = 0; j < 4; ++j)
                if ((hm >> j) & 1u) s_hits[idx++] = (unsigned short)(local0 + j);
        }
    }

    // ---- Phase 4: warp-parallel epoch-checked decoupled lookback (warp 0) ----
    if (wid == 0 && tile > 0u) {
        unsigned excl = 0u;
        int wbase = (int)tile;
        const unsigned long long ep4 = (unsigned long long)(epoch * 4u);
        while (true) {
            int idx = wbase - 32 + lane;
            unsigned long long s;
            unsigned hi, state;
            do {
                if (idx >= 0) {
                    s = *(volatile unsigned long long*)&g_status[idx];
                    hi = (unsigned)(s >> 32);
                    // ready iff same epoch and state != 0
                    state = (hi >> 2 == epoch) ? (hi & 3u) : 0u;
                } else {
                    s = 0ull;           // virtual prefix=0 before tile 0
                    state = 2u;
                }
            } while (__any_sync(0xffffffffu, state == 0u));

            unsigned pmask = __ballot_sync(0xffffffffu, state == 2u);
            unsigned contrib;
            int done;
            if (pmask) {
                int h = 31 - __clz(pmask);       // highest lane holding a prefix
                contrib = (lane >= h) ? (unsigned)(s & 0xffffffffull) : 0u;
                done = 1;
            } else {
                contrib = (unsigned)(s & 0xffffffffull);
                done = 0;
            }
            #pragma unroll
            for (int o = 16; o; o >>= 1)
                contrib += __shfl_down_sync(0xffffffffu, contrib, o);
            contrib = __shfl_sync(0xffffffffu, contrib, 0);
            excl += contrib;
            if (done) break;
            wbase -= 32;
        }
        if (lane == 0) {
            s_excl = excl;
            unsigned long long word =
                ((unsigned long long)(epoch * 4u + 2u) << 32) |
                (unsigned long long)(excl + tile_total);
            __threadfence();
            atomicExch(&g_status[tile], word);
        }
    }
    __syncthreads();
    const unsigned excl = s_excl;

    // ---- Phase 5a: last tile zeroes the invalid tail (output is poisoned) ----
    if (tile == NTILES - 1u) {
        unsigned total = excl + tile_total;
        if (total < MAXPTS) {
            for (unsigned r = total + (unsigned)tid; r < MAXPTS; r += THREADS) {
                float4* f4 = reinterpret_cast<float4*>(out + FEAT_OFF + (size_t)r * 8u);
                f4[0] = make_float4(0.f, 0.f, 0.f, 0.f);
                f4[1] = make_float4(0.f, 0.f, 0.f, 0.f);
                *reinterpret_cast<float4*>(out + COORD_OFF + (size_t)r * 4u) =
                    make_float4(0.f, 0.f, 0.f, 0.f);
            }
        }
    }

    if (excl >= MAXPTS) return;   // nothing from this tile fits

    // ---- Phase 5b: scatter (feature re-reads hit L1/L2 — tile just streamed) ----
    for (unsigned j = tid; j < tile_total; j += THREADS) {
        unsigned rank = excl + j;
        if (rank >= MAXPTS) break;
        unsigned p = p_base + (unsigned)s_hits[j];
        const float* src = in + (size_t)bf * (CH * HW) + p;
        float* f = out + FEAT_OFF + (size_t)rank * 8u;
        #pragma unroll
        for (int c = 0; c < 8; ++c)
            f[c] = __ldg(src + (size_t)c * HW);
        float* cd = out + COORD_OFF + (size_t)rank * 4u;
        cd[0] = (float)(bf >> 3);      // batch = bf / S (S=8)
        cd[1] = (float)(bf & 7u);      // time  = bf % S
        cd[2] = (float)(p / WIDTH);    // y
        cd[3] = (float)(p % WIDTH);    // x
    }
}

// ---------------------------------------------------------------------------
extern "C" void kernel_launch(void* const* d_in, const int* in_sizes, int n_in,
                              void* d_out, int out_size)
{
    const float* frames = (const float*)d_in[0];
    float* out = (float*)d_out;

    voxelizer_kernel<<<NTILES, THREADS>>>(frames, out);
}